// round 7
// baseline (speedup 1.0000x reference)
#include <cuda_runtime.h>
#include <cstdint>

// Threefry variant: 0 = jax_threefry_partitionable (default in modern JAX),
// 1 = legacy split-halves counter scheme.
#ifndef USE_ORIGINAL_THREEFRY
#define USE_ORIGINAL_THREEFRY 0
#endif

namespace {

constexpr int F        = 256;   // N_FEATURES
constexpr int TM       = 64;    // rows per CTA
constexpr int TK       = 32;    // k-chunk staged in smem
constexpr int WPITCH   = 260;   // smem pitch for transposed W chunk
constexpr int NTHREADS = 512;

// smem layout (floats): embT[F][TM] | WsT[TK][WPITCH] | fk0[TM] fk1[TM] (as uint32)
constexpr int EMBT_ELEMS = F * TM;                 // 16384 floats
constexpr int WST_ELEMS  = TK * WPITCH;            // 8320 floats
constexpr int SMEM_BYTES = (EMBT_ELEMS + WST_ELEMS) * 4 + TM * 2 * 4;  // 99328 B

__device__ __forceinline__ uint32_t rotl32(uint32_t x, int d) {
    return __funnelshift_l(x, x, d);   // (x << d) | (x >> (32-d))
}

// JAX threefry2x32: 20 rounds, key schedule injections every 4 rounds.
__device__ __forceinline__ void tf2x32(uint32_t k0, uint32_t k1,
                                       uint32_t x0, uint32_t x1,
                                       uint32_t& o0, uint32_t& o1) {
    uint32_t k2 = k0 ^ k1 ^ 0x1BD11BDAu;
    x0 += k0; x1 += k1;
#define TF_R(r) { x0 += x1; x1 = rotl32(x1, (r)); x1 ^= x0; }
    TF_R(13) TF_R(15) TF_R(26) TF_R(6)   x0 += k1; x1 += k2 + 1u;
    TF_R(17) TF_R(29) TF_R(16) TF_R(24)  x0 += k2; x1 += k0 + 2u;
    TF_R(13) TF_R(15) TF_R(26) TF_R(6)   x0 += k0; x1 += k1 + 3u;
    TF_R(17) TF_R(29) TF_R(16) TF_R(24)  x0 += k1; x1 += k2 + 4u;
    TF_R(13) TF_R(15) TF_R(26) TF_R(6)   x0 += k2; x1 += k0 + 5u;
#undef TF_R
    o0 = x0; o1 = x1;
}

// jax.random.uniform bit mapping: f = bitcast(bits>>9 | 0x3f800000) in [1,2);
// u = (f - 1) * 100 (minval=0 -> lax.max is a no-op).
__device__ __forceinline__ float bits_to_uniform(uint32_t bits) {
    float f = __uint_as_float((bits >> 9) | 0x3f800000u);
    return (f - 1.0f) * 100.0f;
}

__global__ void __launch_bounds__(NTHREADS)
fused_embed_gemm(const float* __restrict__ x,
                 const float* __restrict__ W,
                 const float* __restrict__ bias,
                 float* __restrict__ out) {
    extern __shared__ float smem[];
    float* embT = smem;                         // [F][TM], pitch TM
    float* WsT  = smem + EMBT_ELEMS;            // [TK][WPITCH]
    uint32_t* fk0 = reinterpret_cast<uint32_t*>(smem + EMBT_ELEMS + WST_ELEMS);
    uint32_t* fk1 = fk0 + TM;

    const int t       = threadIdx.x;
    const int rowBase = blockIdx.x * TM;

    // ---- Phase 0: fold_in per row: key' = threefry((0,42), (0, bitcast(x[row]))) ----
    if (t < TM) {
        uint32_t s = __float_as_uint(x[rowBase + t]);
        uint32_t a, b2;
        tf2x32(0u, 42u, 0u, s, a, b2);
        fk0[t] = a; fk1[t] = b2;
    }
    __syncthreads();

    // ---- Phase 1: generate embT[f][row] ----
#if !USE_ORIGINAL_THREEFRY
    // partitionable 32-bit draw: bits[f] = lane0 ^ lane1 of threefry(key, (hi=0, lo=f))
    //   (jax/_src/prng.py _threefry_random_bits_partitionable:
    //    "return lax.convert_element_type(bits1 ^ bits2, dtype)")
    #pragma unroll 2
    for (int rep = 0; rep < (TM * F) / NTHREADS; ++rep) {   // 32 reps
        int idx = t + rep * NTHREADS;
        int row = idx & (TM - 1);
        int f   = idx >> 6;                                  // 0..255
        uint32_t o0, o1;
        tf2x32(fk0[row], fk1[row], 0u, (uint32_t)f, o0, o1);
        embT[f * TM + row] = bits_to_uniform(o0 ^ o1);
    }
#else
    // legacy: counts iota(256) split in halves; block i -> (bits[i], bits[i+128])
    #pragma unroll 2
    for (int rep = 0; rep < (TM * 128) / NTHREADS; ++rep) {  // 16 reps
        int idx = t + rep * NTHREADS;
        int row = idx & (TM - 1);
        int i   = idx >> 6;                                  // 0..127
        uint32_t o0, o1;
        tf2x32(fk0[row], fk1[row], (uint32_t)i, (uint32_t)(i + 128u), o0, o1);
        embT[i * TM + row]         = bits_to_uniform(o0);
        embT[(i + 128) * TM + row] = bits_to_uniform(o1);
    }
#endif
    __syncthreads();

    // ---- Phase 2: out[rowBase..+64, 0..256) = embT^T @ W^T + b ----
    // 16 warps x 32 lanes. warp -> 4 rows; lane -> 8 cols (lane*4+j and 128+lane*4+j).
    const int warp = t >> 5;
    const int lane = t & 31;

    float acc[4][8];
    #pragma unroll
    for (int r = 0; r < 4; ++r)
        #pragma unroll
        for (int j = 0; j < 8; ++j) acc[r][j] = 0.0f;

    const float4 bv0 = *reinterpret_cast<const float4*>(&bias[lane * 4]);
    const float4 bv1 = *reinterpret_cast<const float4*>(&bias[128 + lane * 4]);

    for (int kb = 0; kb < F / TK; ++kb) {
        // Stage W[g][kb*TK + k] -> WsT[k][g] (transposed), 2048 float4 loads.
        #pragma unroll
        for (int j = 0; j < 4; ++j) {
            int lin = t + j * NTHREADS;        // 0..2047
            int g   = lin >> 3;                // 0..255
            int k4  = lin & 7;                 // 0..7
            float4 v = *reinterpret_cast<const float4*>(&W[g * F + kb * TK + k4 * 4]);
            WsT[(k4 * 4 + 0) * WPITCH + g] = v.x;
            WsT[(k4 * 4 + 1) * WPITCH + g] = v.y;
            WsT[(k4 * 4 + 2) * WPITCH + g] = v.z;
            WsT[(k4 * 4 + 3) * WPITCH + g] = v.w;
        }
        __syncthreads();

        #pragma unroll 4
        for (int k = 0; k < TK; ++k) {
            const int f = kb * TK + k;
            const float4 a4 = *reinterpret_cast<const float4*>(&embT[f * TM + warp * 4]);
            const float4 b0 = *reinterpret_cast<const float4*>(&WsT[k * WPITCH + lane * 4]);
            const float4 b1 = *reinterpret_cast<const float4*>(&WsT[k * WPITCH + 128 + lane * 4]);
            const float a[4] = {a4.x, a4.y, a4.z, a4.w};
            const float b[8] = {b0.x, b0.y, b0.z, b0.w, b1.x, b1.y, b1.z, b1.w};
            #pragma unroll
            for (int r = 0; r < 4; ++r)
                #pragma unroll
                for (int j = 0; j < 8; ++j)
                    acc[r][j] += a[r] * b[j];
        }
        __syncthreads();
    }

    // ---- Epilogue: add bias, store ----
    #pragma unroll
    for (int r = 0; r < 4; ++r) {
        const size_t row = (size_t)(rowBase + warp * 4 + r);
        float4 o0, o1;
        o0.x = acc[r][0] + bv0.x; o0.y = acc[r][1] + bv0.y;
        o0.z = acc[r][2] + bv0.z; o0.w = acc[r][3] + bv0.w;
        o1.x = acc[r][4] + bv1.x; o1.y = acc[r][5] + bv1.y;
        o1.z = acc[r][6] + bv1.z; o1.w = acc[r][7] + bv1.w;
        *reinterpret_cast<float4*>(&out[row * F + lane * 4])       = o0;
        *reinterpret_cast<float4*>(&out[row * F + 128 + lane * 4]) = o1;
    }
}

} // anonymous namespace

extern "C" void kernel_launch(void* const* d_in, const int* in_sizes, int n_in,
                              void* d_out, int out_size) {
    const float* x    = (const float*)d_in[0];   // [256*512] fp32
    const float* W    = (const float*)d_in[1];   // [256,256] fp32 row-major (W[g][f])
    const float* bias = (const float*)d_in[2];   // [256]
    float* out        = (float*)d_out;           // [131072, 256]

    const int nrows = in_sizes[0];               // 131072
    const int grid  = nrows / TM;                // 2048

    cudaFuncSetAttribute(fused_embed_gemm,
                         cudaFuncAttributeMaxDynamicSharedMemorySize, SMEM_BYTES);
    fused_embed_gemm<<<grid, NTHREADS, SMEM_BYTES>>>(x, W, bias, out);
}

// round 8
// speedup vs baseline: 1.2032x; 1.2032x over previous
#include <cuda_runtime.h>
#include <cstdint>

#ifndef USE_ORIGINAL_THREEFRY
#define USE_ORIGINAL_THREEFRY 0
#endif

namespace {

constexpr int F        = 256;   // N_FEATURES
constexpr int TM       = 64;    // rows per CTA
constexpr int TK       = 32;    // k-chunk staged in smem
constexpr int WPITCH   = 260;   // smem pitch (multiple of 4 floats, odd*4 -> conflict-free)
constexpr int NTHREADS = 512;

constexpr int EMBT_ELEMS = F * TM;                 // 16384 floats
constexpr int WST_ELEMS  = TK * WPITCH;            // 8320 floats
constexpr int SMEM_BYTES = (EMBT_ELEMS + WST_ELEMS) * 4 + TM * 2 * 4;  // 99328 B

__device__ __forceinline__ uint32_t rotl32(uint32_t x, int d) {
    return __funnelshift_l(x, x, d);
}

// JAX threefry2x32: 20 rounds, key injections every 4 rounds.
__device__ __forceinline__ void tf2x32(uint32_t k0, uint32_t k1,
                                       uint32_t x0, uint32_t x1,
                                       uint32_t& o0, uint32_t& o1) {
    uint32_t k2 = k0 ^ k1 ^ 0x1BD11BDAu;
    x0 += k0; x1 += k1;
#define TF_R(r) { x0 += x1; x1 = rotl32(x1, (r)); x1 ^= x0; }
    TF_R(13) TF_R(15) TF_R(26) TF_R(6)   x0 += k1; x1 += k2 + 1u;
    TF_R(17) TF_R(29) TF_R(16) TF_R(24)  x0 += k2; x1 += k0 + 2u;
    TF_R(13) TF_R(15) TF_R(26) TF_R(6)   x0 += k0; x1 += k1 + 3u;
    TF_R(17) TF_R(29) TF_R(16) TF_R(24)  x0 += k1; x1 += k2 + 4u;
    TF_R(13) TF_R(15) TF_R(26) TF_R(6)   x0 += k2; x1 += k0 + 5u;
#undef TF_R
    o0 = x0; o1 = x1;
}

__device__ __forceinline__ float bits_to_uniform(uint32_t bits) {
    float f = __uint_as_float((bits >> 9) | 0x3f800000u);
    return (f - 1.0f) * 100.0f;
}

// ---- packed fp32x2 helpers (sm_100+): 2 FMAs per fma-pipe slot ----
__device__ __forceinline__ uint64_t f32x2_dup(float x) {
    uint64_t r;
    asm("mov.b64 %0, {%1, %1};" : "=l"(r) : "f"(x));
    return r;
}
__device__ __forceinline__ uint64_t f32x2_fma(uint64_t a, uint64_t b, uint64_t c) {
    uint64_t d;
    asm("fma.rn.f32x2 %0, %1, %2, %3;" : "=l"(d) : "l"(a), "l"(b), "l"(c));
    return d;
}
__device__ __forceinline__ float f32x2_lo(uint64_t v) {
    return __uint_as_float((uint32_t)v);
}
__device__ __forceinline__ float f32x2_hi(uint64_t v) {
    return __uint_as_float((uint32_t)(v >> 32));
}

__global__ void __launch_bounds__(NTHREADS, 2)
fused_embed_gemm(const float* __restrict__ x,
                 const float* __restrict__ W,
                 const float* __restrict__ bias,
                 float* __restrict__ out) {
    extern __shared__ float smem[];
    float* embT = smem;                         // [F][TM]
    float* WsT  = smem + EMBT_ELEMS;            // [TK][WPITCH]
    uint32_t* fk0 = reinterpret_cast<uint32_t*>(smem + EMBT_ELEMS + WST_ELEMS);
    uint32_t* fk1 = fk0 + TM;

    const int t       = threadIdx.x;
    const int rowBase = blockIdx.x * TM;

    // ---- Phase 0: fold_in per row: key' = threefry((0,42), (0, bitcast(x[row]))) ----
    if (t < TM) {
        uint32_t s = __float_as_uint(x[rowBase + t]);
        uint32_t a, b2;
        tf2x32(0u, 42u, 0u, s, a, b2);
        fk0[t] = a; fk1[t] = b2;
    }
    __syncthreads();

    // ---- Phase 1: generate embT[f][row] ----
#if !USE_ORIGINAL_THREEFRY
    // partitionable 32-bit draw: bits[f] = lane0 ^ lane1 of threefry(key, (0, f))
    #pragma unroll 2
    for (int rep = 0; rep < (TM * F) / NTHREADS; ++rep) {   // 32 reps
        int idx = t + rep * NTHREADS;
        int row = idx & (TM - 1);
        int f   = idx >> 6;
        uint32_t o0, o1;
        tf2x32(fk0[row], fk1[row], 0u, (uint32_t)f, o0, o1);
        embT[f * TM + row] = bits_to_uniform(o0 ^ o1);
    }
#else
    #pragma unroll 2
    for (int rep = 0; rep < (TM * 128) / NTHREADS; ++rep) {
        int idx = t + rep * NTHREADS;
        int row = idx & (TM - 1);
        int i   = idx >> 6;
        uint32_t o0, o1;
        tf2x32(fk0[row], fk1[row], (uint32_t)i, (uint32_t)(i + 128u), o0, o1);
        embT[i * TM + row]         = bits_to_uniform(o0);
        embT[(i + 128) * TM + row] = bits_to_uniform(o1);
    }
#endif
    __syncthreads();

    // ---- Phase 2: out[rowBase..+64, :] = embT^T @ W^T + b, packed f32x2 FMA ----
    // 16 warps = 8 rowGroups x 2 colGroups. Warp tile: 8 rows x 128 cols.
    // Thread tile: 8 rows x 4 cols (cols = cg + lane*4 .. +3).
    // Accumulators packed along rows: acc2[rp][c] = {row 2rp, row 2rp+1} at col c.
    const int warp   = t >> 5;
    const int lane   = t & 31;
    const int rowOff = (warp >> 1) * 8;           // 0,8,...,56
    const int cg     = (warp & 1) * 128;          // 0 or 128

    uint64_t acc2[4][4];
    #pragma unroll
    for (int rp = 0; rp < 4; ++rp)
        #pragma unroll
        for (int c = 0; c < 4; ++c) acc2[rp][c] = 0ull;

    for (int kb = 0; kb < F / TK; ++kb) {
        // Stage W[g][kb*TK + k] -> WsT[k][g] (transposed).
        #pragma unroll
        for (int j = 0; j < 4; ++j) {
            int lin = t + j * NTHREADS;        // 0..2047
            int g   = lin >> 3;                // 0..255
            int k4  = lin & 7;                 // 0..7
            float4 v = *reinterpret_cast<const float4*>(&W[g * F + kb * TK + k4 * 4]);
            WsT[(k4 * 4 + 0) * WPITCH + g] = v.x;
            WsT[(k4 * 4 + 1) * WPITCH + g] = v.y;
            WsT[(k4 * 4 + 2) * WPITCH + g] = v.z;
            WsT[(k4 * 4 + 3) * WPITCH + g] = v.w;
        }
        __syncthreads();

        const float* embBase = &embT[(kb * TK) * TM + rowOff];
        const float* wBase   = &WsT[cg + lane * 4];

        #pragma unroll 4
        for (int k = 0; k < TK; ++k) {
            // a: 8 rows, natural f32x2 pairs straight out of LDS.128 (broadcast)
            double2 a01 = *reinterpret_cast<const double2*>(embBase + k * TM);
            double2 a23 = *reinterpret_cast<const double2*>(embBase + k * TM + 4);
            uint64_t ap[4];
            ap[0] = __double_as_longlong(a01.x);   // rows 0,1
            ap[1] = __double_as_longlong(a01.y);   // rows 2,3
            ap[2] = __double_as_longlong(a23.x);   // rows 4,5
            ap[3] = __double_as_longlong(a23.y);   // rows 6,7

            // b: 4 cols, duplicated into both halves
            float4 bv = *reinterpret_cast<const float4*>(wBase + k * WPITCH);
            uint64_t bd[4];
            bd[0] = f32x2_dup(bv.x); bd[1] = f32x2_dup(bv.y);
            bd[2] = f32x2_dup(bv.z); bd[3] = f32x2_dup(bv.w);

            #pragma unroll
            for (int rp = 0; rp < 4; ++rp)
                #pragma unroll
                for (int c = 0; c < 4; ++c)
                    acc2[rp][c] = f32x2_fma(ap[rp], bd[c], acc2[rp][c]);
        }
        __syncthreads();
    }

    // ---- Epilogue: add bias, store 8 rows x 4 cols ----
    const float4 bv = *reinterpret_cast<const float4*>(&bias[cg + lane * 4]);
    #pragma unroll
    for (int rp = 0; rp < 4; ++rp) {
        const size_t r0 = (size_t)(rowBase + rowOff + 2 * rp);
        float4 lo, hi;
        lo.x = f32x2_lo(acc2[rp][0]) + bv.x;  hi.x = f32x2_hi(acc2[rp][0]) + bv.x;
        lo.y = f32x2_lo(acc2[rp][1]) + bv.y;  hi.y = f32x2_hi(acc2[rp][1]) + bv.y;
        lo.z = f32x2_lo(acc2[rp][2]) + bv.z;  hi.z = f32x2_hi(acc2[rp][2]) + bv.z;
        lo.w = f32x2_lo(acc2[rp][3]) + bv.w;  hi.w = f32x2_hi(acc2[rp][3]) + bv.w;
        *reinterpret_cast<float4*>(&out[r0 * F + cg + lane * 4])       = lo;
        *reinterpret_cast<float4*>(&out[(r0 + 1) * F + cg + lane * 4]) = hi;
    }
}

} // anonymous namespace

extern "C" void kernel_launch(void* const* d_in, const int* in_sizes, int n_in,
                              void* d_out, int out_size) {
    const float* x    = (const float*)d_in[0];   // [256*512] fp32
    const float* W    = (const float*)d_in[1];   // [256,256] fp32 row-major (W[g][f])
    const float* bias = (const float*)d_in[2];   // [256]
    float* out        = (float*)d_out;           // [131072, 256]

    const int nrows = in_sizes[0];               // 131072
    const int grid  = nrows / TM;                // 2048

    cudaFuncSetAttribute(fused_embed_gemm,
                         cudaFuncAttributeMaxDynamicSharedMemorySize, SMEM_BYTES);
    fused_embed_gemm<<<grid, NTHREADS, SMEM_BYTES>>>(x, W, bias, out);
}